// round 4
// baseline (speedup 1.0000x reference)
#include <cuda_runtime.h>
#include <cuda_bf16.h>
#include <cstdint>

// B = 8192 rows, T = 4096 features, G = 64 groups.
// Group sizes cycle (32, 64, 96, 64) x 16; all boundaries are multiples of 32,
// so each aligned 32-elem chunk belongs to exactly one group (128 chunks/row).
// Output: d_out[0..B) = Z (fp32), d_out[B..B+B*64) = a (fp32 row-major [B,64]).
//
// R4: cp.async (LDGSTS) staging pipeline. MLP lives in SMEM, not registers:
//   - DEPTH=2 stages of 16KB/row, regs stay low (~30) -> 6 CTAs/SM
//   - persistent strided grid of 888 CTAs (6 * 148) -> single wave
//   - async copies keep DRAM busy through __syncthreads + epilogue
//   - each thread reads back only the bytes it copied -> no barrier needed
//     for stage visibility/reuse; empty commit_groups keep wait counts aligned

#define T_DIM     4096
#define G_DIM     64
#define NTHREADS  256
#define GRID      888          // 6 CTAs/SM * 148 SMs, single wave
#define DEPTH     2

__device__ __forceinline__ void cp_async16(uint32_t dst_smem, const float4* src) {
    asm volatile("cp.async.cg.shared.global [%0], [%1], 16;"
                 :: "r"(dst_smem), "l"(src) : "memory");
}
#define CP_COMMIT() asm volatile("cp.async.commit_group;" ::: "memory")
#define CP_WAIT(n)  asm volatile("cp.async.wait_group %0;" :: "n"(n) : "memory")

__global__ __launch_bounds__(NTHREADS)
void agp_kernel(const float* __restrict__ H,
                const float* __restrict__ score_w,
                const float* __restrict__ score_b,
                float* __restrict__ out, int B)
{
    const int tid = threadIdx.x;
    const int bid = blockIdx.x;

    __shared__ float stage[DEPTH][T_DIM];        // 2 x 16KB staging
    __shared__ float chunk_sum[2][T_DIM / 32];   // ping-pong, 2 x 128
    __shared__ float s_w, s_b;
    if (tid == 0) { s_w = score_w[0]; s_b = score_b[0]; }

    const float4* base4 = reinterpret_cast<const float4*>(H);

    // per-thread smem addresses for this thread's 4 float4 slots in each stage
    uint32_t st_addr[DEPTH];
    #pragma unroll
    for (int s = 0; s < DEPTH; ++s)
        st_addr[s] = (uint32_t)__cvta_generic_to_shared(&stage[s][0]) + tid * 16;

    // ---- prologue: issue DEPTH rows ----
    #pragma unroll
    for (int s = 0; s < DEPTH; ++s) {
        int r = bid + s * GRID;
        if (r < B) {
            const float4* src = base4 + (size_t)r * (T_DIM / 4) + tid;
            #pragma unroll
            for (int k = 0; k < 4; ++k)
                cp_async16(st_addr[s] + k * 4096, src + k * NTHREADS);
        }
        CP_COMMIT();                 // empty group ok if out of range
    }

    const int   c_start[4] = {0, 1, 3, 6};
    const int   c_cnt[4]   = {1, 2, 3, 2};
    const float inv_sz[4]  = {1.0f/32.0f, 1.0f/64.0f, 1.0f/96.0f, 1.0f/64.0f};

    int row = bid;
    int i = 0;
    #pragma unroll 1
    while (row < B) {
        const int s = i & (DEPTH - 1);
        const int pp = i & 1;

        CP_WAIT(DEPTH - 1);          // this row's stage is complete

        // ---- reduce my own staged data -> chunk sums ----
        const float4* my = reinterpret_cast<const float4*>(
            reinterpret_cast<const char*>(&stage[s][0]) + tid * 16);
        #pragma unroll
        for (int k = 0; k < 4; ++k) {
            float4 vv = my[k * NTHREADS];
            float sum = (vv.x + vv.y) + (vv.z + vv.w);
            sum += __shfl_xor_sync(0xffffffffu, sum, 1);
            sum += __shfl_xor_sync(0xffffffffu, sum, 2);
            sum += __shfl_xor_sync(0xffffffffu, sum, 4);
            if ((tid & 7) == 0)
                chunk_sum[pp][(tid >> 3) + 32 * k] = sum;
        }

        // ---- refill this stage with row + DEPTH*GRID ----
        {
            int rn = row + DEPTH * GRID;
            if (rn < B) {
                const float4* src = base4 + (size_t)rn * (T_DIM / 4) + tid;
                #pragma unroll
                for (int k = 0; k < 4; ++k)
                    cp_async16(st_addr[s] + k * 4096, src + k * NTHREADS);
            }
            CP_COMMIT();             // always exactly one group per iteration
        }

        __syncthreads();             // chunk_sum[pp] visible to warp 0

        // ---- warp 0: groups -> softmax -> Z (async copies still in flight) ----
        if (tid < 32) {
            const float w = s_w, bias = s_b;
            float Gm[2], sc[2];
            #pragma unroll
            for (int j = 0; j < 2; ++j) {
                int g    = tid + 32 * j;
                int sub  = g & 3;
                int base = (g >> 2) * 8 + c_start[sub];
                float acc = 0.0f;
                #pragma unroll
                for (int c = 0; c < 3; ++c)
                    if (c < c_cnt[sub]) acc += chunk_sum[pp][base + c];
                Gm[j] = acc * inv_sz[sub];
                sc[j] = Gm[j] * w + bias;
            }

            float mx = fmaxf(sc[0], sc[1]);
            #pragma unroll
            for (int d = 16; d > 0; d >>= 1)
                mx = fmaxf(mx, __shfl_xor_sync(0xffffffffu, mx, d));

            float p0 = expf(sc[0] - mx);
            float p1 = expf(sc[1] - mx);
            float ssum = p0 + p1;
            #pragma unroll
            for (int d = 16; d > 0; d >>= 1)
                ssum += __shfl_xor_sync(0xffffffffu, ssum, d);
            float inv = 1.0f / ssum;
            float a0 = p0 * inv;
            float a1 = p1 * inv;

            float zp = a0 * Gm[0] + a1 * Gm[1];
            #pragma unroll
            for (int d = 16; d > 0; d >>= 1)
                zp += __shfl_xor_sync(0xffffffffu, zp, d);

            float* a_out = out + B + (size_t)row * G_DIM;
            a_out[tid]      = a0;
            a_out[tid + 32] = a1;
            if (tid == 0) out[row] = zp;
        }

        row += GRID;
        ++i;
    }
}

extern "C" void kernel_launch(void* const* d_in, const int* in_sizes, int n_in,
                              void* d_out, int out_size)
{
    const float* H  = (const float*)d_in[0];   // [B, 4096]
    const float* sw = (const float*)d_in[1];   // [1,1]
    const float* sb = (const float*)d_in[2];   // [1]
    float* out = (float*)d_out;

    int B = in_sizes[0] / T_DIM;               // 8192
    agp_kernel<<<GRID, NTHREADS>>>(H, sw, sb, out, B);
}

// round 5
// speedup vs baseline: 1.2185x; 1.2185x over previous
#include <cuda_runtime.h>
#include <cuda_bf16.h>

// B = 8192 rows, T = 4096 features, G = 64 groups.
// Group sizes cycle (32, 64, 96, 64) x 16; all boundaries are multiples of 32,
// so each aligned 32-elem chunk belongs to exactly one group (128 chunks/row).
// Output: d_out[0..B) = Z (fp32), d_out[B..B+B*64) = a (fp32 row-major [B,64]).
//
// R5 = R1 load structure (the proven one: 4 x LDG.128/thread, regs=32) with:
//  - 512 threads / 2 rows per CTA (halves barriers + CTA churn; 2 parallel
//    epilogue warps). __launch_bounds__(512,4) pins regs <= 32 -> 64 warps/SM.
//  - __expf instead of expf (epilogue was latency-bound on the exp lib call)
//  - ssum and Z reduction trees interleaved (one fewer serial shuffle tree)
//  - __ldcs streaming loads (read-once data, evict-first)

#define T_DIM    4096
#define G_DIM    64
#define NTHREADS 512
#define ROWS     2

__global__ __launch_bounds__(NTHREADS, 4)
void agp_kernel(const float* __restrict__ H,
                const float* __restrict__ score_w,
                const float* __restrict__ score_b,
                float* __restrict__ out, int B)
{
    const int tid = threadIdx.x;
    const int r   = tid >> 8;          // row within CTA (0,1)
    const int t   = tid & 255;         // thread within row sub-block
    const int b   = blockIdx.x * ROWS + r;

    __shared__ float chunk_sum[ROWS][T_DIM / 32];   // 2 x 128

    // --- Phase 1: identical per-thread load/reduce as R1 (regs stay 32) ---
    const float4* rp = reinterpret_cast<const float4*>(H) + (size_t)b * (T_DIM / 4);
    #pragma unroll
    for (int k = 0; k < 4; ++k) {
        float4 v = __ldcs(rp + t + 256 * k);
        float s = (v.x + v.y) + (v.z + v.w);
        // aligned 8-lane butterfly -> one 32-elem chunk sum
        s += __shfl_xor_sync(0xffffffffu, s, 1);
        s += __shfl_xor_sync(0xffffffffu, s, 2);
        s += __shfl_xor_sync(0xffffffffu, s, 4);
        if ((t & 7) == 0)
            chunk_sum[r][(t >> 3) + 32 * k] = s;
    }
    __syncthreads();

    // --- Phase 2: warps 0 and 1 each do one row's epilogue in parallel ---
    if (tid < 64) {
        const int er   = tid >> 5;
        const int lane = tid & 31;
        const int eb   = blockIdx.x * ROWS + er;

        const float w    = __ldg(score_w);
        const float bias = __ldg(score_b);

        // per-subgroup (g & 3): chunk start within 8-chunk cycle, count, 1/size
        const int   c_start[4] = {0, 1, 3, 6};
        const int   c_cnt[4]   = {1, 2, 3, 2};
        const float inv_sz[4]  = {1.0f/32.0f, 1.0f/64.0f, 1.0f/96.0f, 1.0f/64.0f};

        float Gm[2], sc[2];
        #pragma unroll
        for (int j = 0; j < 2; ++j) {
            int g    = lane + 32 * j;
            int sub  = g & 3;
            int base = (g >> 2) * 8 + c_start[sub];
            float s = 0.0f;
            #pragma unroll
            for (int c = 0; c < 3; ++c)
                if (c < c_cnt[sub]) s += chunk_sum[er][base + c];
            Gm[j] = s * inv_sz[sub];
            sc[j] = Gm[j] * w + bias;
        }

        // max tree (needed before exp)
        float mx = fmaxf(sc[0], sc[1]);
        #pragma unroll
        for (int d = 16; d > 0; d >>= 1)
            mx = fmaxf(mx, __shfl_xor_sync(0xffffffffu, mx, d));

        float p0 = __expf(sc[0] - mx);
        float p1 = __expf(sc[1] - mx);

        // interleaved trees: ssum = sum(p), pz = sum(p * G)  (independent)
        float ssum = p0 + p1;
        float pz   = p0 * Gm[0] + p1 * Gm[1];
        #pragma unroll
        for (int d = 16; d > 0; d >>= 1) {
            ssum += __shfl_xor_sync(0xffffffffu, ssum, d);
            pz   += __shfl_xor_sync(0xffffffffu, pz, d);
        }
        float inv = 1.0f / ssum;

        float* a_out = out + B + (size_t)eb * G_DIM;
        a_out[lane]      = p0 * inv;
        a_out[lane + 32] = p1 * inv;
        if (lane == 0) out[eb] = pz * inv;   // Z = sum(a*G) = pz / ssum
    }
}

extern "C" void kernel_launch(void* const* d_in, const int* in_sizes, int n_in,
                              void* d_out, int out_size)
{
    const float* H  = (const float*)d_in[0];   // [B, 4096]
    const float* sw = (const float*)d_in[1];   // [1,1]
    const float* sb = (const float*)d_in[2];   // [1]
    float* out = (float*)d_out;

    int B = in_sizes[0] / T_DIM;               // 8192
    agp_kernel<<<B / ROWS, NTHREADS>>>(H, sw, sb, out, B);
}

// round 6
// speedup vs baseline: 1.2449x; 1.0217x over previous
#include <cuda_runtime.h>
#include <cuda_bf16.h>

// B = 8192 rows, T = 4096 features, G = 64 groups.
// Group sizes cycle (32, 64, 96, 64) x 16; all boundaries are multiples of 32,
// so each aligned 32-elem chunk belongs to exactly one group (128 chunks/row).
// Output: d_out[0..B) = Z (fp32), d_out[B..B+B*64) = a (fp32 row-major [B,64]).
//
// R6 = R1 (measured-best geometry: 256 thr, 1 row/CTA, grid=8192, regs=32,
// occ 86%) + non-structural epilogue micro-opts only:
//   - __expf (MUFU) instead of expf
//   - interleaved ssum / Z=sum(p*G) shuffle trees, Z = pz/ssum
//   - __ldg scalars directly in warp 0 (no smem broadcast)
// Load stream is byte-identical to R1 (plain LDG.128; __ldcs measured worse).

#define T_DIM    4096
#define G_DIM    64
#define NTHREADS 256

__global__ __launch_bounds__(NTHREADS, 8)
void agp_kernel(const float* __restrict__ H,
                const float* __restrict__ score_w,
                const float* __restrict__ score_b,
                float* __restrict__ out, int B)
{
    const int b   = blockIdx.x;
    const int tid = threadIdx.x;

    __shared__ float chunk_sum[T_DIM / 32];   // 128 chunk sums

    const float4* row4 = reinterpret_cast<const float4*>(H + (size_t)b * T_DIM);

    // --- Phase 1: 4 coalesced LDG.128 per thread, butterfly to chunk sums ---
    #pragma unroll
    for (int k = 0; k < 4; ++k) {
        float4 v = row4[tid + NTHREADS * k];
        float s = (v.x + v.y) + (v.z + v.w);
        s += __shfl_xor_sync(0xffffffffu, s, 1);
        s += __shfl_xor_sync(0xffffffffu, s, 2);
        s += __shfl_xor_sync(0xffffffffu, s, 4);
        if ((tid & 7) == 0)
            chunk_sum[(tid >> 3) + 32 * k] = s;
    }
    __syncthreads();

    // --- Phase 2: warp 0 does groups -> softmax -> Z ---
    if (tid < 32) {
        const float w    = __ldg(score_w);
        const float bias = __ldg(score_b);

        // per-subgroup (g & 3): chunk start within 8-chunk cycle, count, 1/size
        const int   c_start[4] = {0, 1, 3, 6};
        const int   c_cnt[4]   = {1, 2, 3, 2};
        const float inv_sz[4]  = {1.0f/32.0f, 1.0f/64.0f, 1.0f/96.0f, 1.0f/64.0f};

        float Gm[2], sc[2];
        #pragma unroll
        for (int j = 0; j < 2; ++j) {
            int g    = tid + 32 * j;
            int sub  = g & 3;
            int base = (g >> 2) * 8 + c_start[sub];
            float s = 0.0f;
            #pragma unroll
            for (int c = 0; c < 3; ++c)
                if (c < c_cnt[sub]) s += chunk_sum[base + c];
            Gm[j] = s * inv_sz[sub];
            sc[j] = Gm[j] * w + bias;
        }

        // max tree (required before exp)
        float mx = fmaxf(sc[0], sc[1]);
        #pragma unroll
        for (int d = 16; d > 0; d >>= 1)
            mx = fmaxf(mx, __shfl_xor_sync(0xffffffffu, mx, d));

        float p0 = __expf(sc[0] - mx);
        float p1 = __expf(sc[1] - mx);

        // interleaved independent trees: ssum = sum(p), pz = sum(p*G)
        float ssum = p0 + p1;
        float pz   = p0 * Gm[0] + p1 * Gm[1];
        #pragma unroll
        for (int d = 16; d > 0; d >>= 1) {
            ssum += __shfl_xor_sync(0xffffffffu, ssum, d);
            pz   += __shfl_xor_sync(0xffffffffu, pz, d);
        }
        float inv = 1.0f / ssum;

        float* a_out = out + B + (size_t)b * G_DIM;
        a_out[tid]      = p0 * inv;
        a_out[tid + 32] = p1 * inv;
        if (tid == 0) out[b] = pz * inv;   // Z = sum(a*G) = pz / ssum
    }
}

extern "C" void kernel_launch(void* const* d_in, const int* in_sizes, int n_in,
                              void* d_out, int out_size)
{
    const float* H  = (const float*)d_in[0];   // [B, 4096]
    const float* sw = (const float*)d_in[1];   // [1,1]
    const float* sb = (const float*)d_in[2];   // [1]
    float* out = (float*)d_out;

    int B = in_sizes[0] / T_DIM;               // 8192
    agp_kernel<<<B, NTHREADS>>>(H, sw, sb, out, B);
}